// round 4
// baseline (speedup 1.0000x reference)
#include <cuda_runtime.h>
#include <math.h>

#define N_  64
#define C_  512
#define M_  1600   // H*W = 40*40
#define K_  64

// ---------------- device scratch (no allocations allowed) ----------------
__device__ float g_assign[(size_t)N_*K_*M_];  // A'[n][k][m] = softmax * invnorm (26 MB)
__device__ float g_norms[N_*M_];              // max(||x[n,:,m]||, eps)
__device__ float g_agg[(size_t)N_*K_*C_];     // agg[n][k][c] (8.4 MB)
__device__ float g_wt[C_*K_];                 // W transposed: [c][k]
__device__ float g_gssq[N_];                  // per-image global sumsq

// ---------------- packed f32x2 helpers (sm_100+) ----------------
__device__ __forceinline__ unsigned long long pack2(float lo, float hi) {
    unsigned long long r;
    asm("mov.b64 %0, {%1,%2};" : "=l"(r) : "f"(lo), "f"(hi));
    return r;
}
__device__ __forceinline__ void unpack2(unsigned long long v, float& lo, float& hi) {
    asm("mov.b64 {%0,%1}, %2;" : "=f"(lo), "=f"(hi) : "l"(v));
}
__device__ __forceinline__ void ffma2(unsigned long long& d, unsigned long long a,
                                      unsigned long long b) {
    asm("fma.rn.f32x2 %0, %1, %2, %0;" : "+l"(d) : "l"(a), "l"(b));
}

// ---------------- K0: zero accumulators + transpose W ----------------
__global__ void k_init(const float* __restrict__ conv_w) {
    int idx = blockIdx.x * 256 + threadIdx.x;      // grid 128 x 256 = 32768 = C*K
    if (idx < N_) g_gssq[idx] = 0.f;
    int c = idx >> 6, k = idx & 63;
    g_wt[idx] = conv_w[k * C_ + c];
}

// ---------------- K1: GEMM1 + fused L2-norm + softmax ----------------
// One thread owns one pixel column m and all 64 cluster logits (32 f32x2 pairs,
// packed over k). ssq for the channel L2-norm accumulates in the same loop.
// Grid: 640 blocks (64 n x 10 m-tiles of 160), 160 threads.
__global__ __launch_bounds__(160) void k_logits(const float* __restrict__ x,
                                                const float* __restrict__ conv_b) {
    __shared__ __align__(16) float ws[128 * 64];   // 32 KB chunk of W^T: [c_local][k]
    __shared__ float sb[K_];
    const int tid = threadIdx.x;
    const int n = blockIdx.x / 10;
    const int m = (blockIdx.x % 10) * 160 + tid;
    if (tid < K_) sb[tid] = conv_b[tid];

    const float* xp = x + (size_t)n * C_ * M_ + m;

    unsigned long long acc[32];
#pragma unroll
    for (int j = 0; j < 32; j++) acc[j] = 0ull;
    float ssq = 0.f;

    for (int cc = 0; cc < C_; cc += 128) {
        __syncthreads();
        for (int i = tid; i < 128 * 64; i += 160) ws[i] = g_wt[cc * 64 + i];
        __syncthreads();
#pragma unroll 1
        for (int c = 0; c < 128; c += 4) {
            float xv[4];
#pragma unroll
            for (int u = 0; u < 4; u++) xv[u] = xp[(size_t)(cc + c + u) * M_];
#pragma unroll
            for (int u = 0; u < 4; u++) {
                ssq = fmaf(xv[u], xv[u], ssq);
                unsigned long long xx = pack2(xv[u], xv[u]);
                const ulonglong2* wrow =
                    reinterpret_cast<const ulonglong2*>(ws + (c + u) * 64);
#pragma unroll
                for (int j = 0; j < 16; j++) {
                    ulonglong2 w4 = wrow[j];
                    ffma2(acc[2 * j + 0], xx, w4.x);
                    ffma2(acc[2 * j + 1], xx, w4.y);
                }
            }
        }
    }

    // epilogue: scale by invnorm, add bias, thread-local softmax over k
    const float nrm = fmaxf(sqrtf(ssq), 1e-12f);
    const float inv = 1.0f / nrm;
    float lg[64];
#pragma unroll
    for (int j = 0; j < 32; j++) {
        float a, b;
        unpack2(acc[j], a, b);
        lg[2 * j + 0] = fmaf(a, inv, sb[2 * j + 0]);
        lg[2 * j + 1] = fmaf(b, inv, sb[2 * j + 1]);
    }
    float mx = -1e30f;
#pragma unroll
    for (int k = 0; k < K_; k++) mx = fmaxf(mx, lg[k]);
    float s = 0.f;
#pragma unroll
    for (int k = 0; k < K_; k++) { float e = __expf(lg[k] - mx); lg[k] = e; s += e; }
    const float rs = inv / s;   // softmax * invnorm in one multiply

    float* ap = g_assign + (size_t)n * K_ * M_ + m;
#pragma unroll
    for (int k = 0; k < K_; k++) ap[(size_t)k * M_] = lg[k] * rs;  // coalesced per k
    g_norms[n * M_ + m] = nrm;
}

// ---------------- K2: GEMM2  agg[n,k,c] = sum_m A'[k,m] * x[c,m] ----------------
// Block: one (n, 128-wide c tile), 256 threads as 16x16; thread owns 4k x 8c
// (16 f32x2 pairs packed over c). x tile transposed into shared so c-pairs are
// contiguous. Grid: (4, 64).
#define TM 32
#define XPITCH 132
__global__ __launch_bounds__(256) void k_agg(const float* __restrict__ x) {
    __shared__ float sA[64 * 33];
    __shared__ __align__(16) float xs[TM * XPITCH];
    const int tid = threadIdx.x;
    const int n = blockIdx.y;
    const int c0 = blockIdx.x * 128;
    const int tk = tid >> 4, tc = tid & 15;
    const int kbase = 4 * tk, cbase = 8 * tc;

    const float* Ap = g_assign + (size_t)n * K_ * M_;
    const float* xp = x + (size_t)n * C_ * M_ + (size_t)c0 * M_;

    unsigned long long acc[16];
#pragma unroll
    for (int i = 0; i < 16; i++) acc[i] = 0ull;

    for (int mb = 0; mb < M_; mb += TM) {
        __syncthreads();
#pragma unroll
        for (int i = tid; i < 64 * TM; i += 256) {            // A' tile 64x32
            int k = i >> 5, mm = i & 31;
            sA[k * 33 + mm] = Ap[(size_t)k * M_ + mb + mm];
        }
#pragma unroll
        for (int i = tid; i < 128 * TM; i += 256) {           // x tile 128x32 (transposed)
            int c = i >> 5, mm = i & 31;
            xs[mm * XPITCH + c] = xp[(size_t)c * M_ + mb + mm];
        }
        __syncthreads();
#pragma unroll 1
        for (int mm = 0; mm < TM; mm++) {
            unsigned long long av[4];
#pragma unroll
            for (int i = 0; i < 4; i++) {
                float a = sA[(kbase + i) * 33 + mm];
                av[i] = pack2(a, a);
            }
            const ulonglong2* xr =
                reinterpret_cast<const ulonglong2*>(xs + mm * XPITCH + cbase);
            ulonglong2 x01 = xr[0], x23 = xr[1];
#pragma unroll
            for (int i = 0; i < 4; i++) {
                ffma2(acc[i * 4 + 0], av[i], x01.x);
                ffma2(acc[i * 4 + 1], av[i], x01.y);
                ffma2(acc[i * 4 + 2], av[i], x23.x);
                ffma2(acc[i * 4 + 3], av[i], x23.y);
            }
        }
    }

    float* op = g_agg + ((size_t)n * K_ + kbase) * C_ + c0 + cbase;
#pragma unroll
    for (int i = 0; i < 4; i++)
#pragma unroll
        for (int j = 0; j < 4; j++) {
            float a, b;
            unpack2(acc[i * 4 + j], a, b);
            op[(size_t)i * C_ + 2 * j + 0] = a;
            op[(size_t)i * C_ + 2 * j + 1] = b;
        }
}

// ---------------- K3: finalize per (n,k) row: a_sum, residual, intra-norm ----
__global__ __launch_bounds__(128) void k_final(const float* __restrict__ cent,
                                               float* __restrict__ out) {
    const int n = blockIdx.x >> 6;
    const int k = blockIdx.x & 63;
    const int tid = threadIdx.x;
    __shared__ float red[128];

    // a_sum[n,k] = sum_m A'[n,k,m] * norm[n,m]
    const float* ap = g_assign + ((size_t)n * K_ + k) * M_;
    const float* np = g_norms + n * M_;
    float s = 0.f;
    for (int m = tid; m < M_; m += 128) s = fmaf(ap[m], np[m], s);
    red[tid] = s;
    __syncthreads();
    for (int off = 64; off > 0; off >>= 1) {
        if (tid < off) red[tid] += red[tid + off];
        __syncthreads();
    }
    const float asum = red[0];
    __syncthreads();

    const float* gp = g_agg + ((size_t)n * K_ + k) * C_;
    const float* cp = cent + k * C_;
    float v[4];
    float ssq = 0.f;
#pragma unroll
    for (int i = 0; i < 4; i++) {
        int c = tid + i * 128;
        v[i] = gp[c] - asum * cp[c];
        ssq = fmaf(v[i], v[i], ssq);
    }
    red[tid] = ssq;
    __syncthreads();
    for (int off = 64; off > 0; off >>= 1) {
        if (tid < off) red[tid] += red[tid + off];
        __syncthreads();
    }
    const float rssq = red[0];
    const float inv = 1.0f / fmaxf(sqrtf(rssq), 1e-12f);
    float* op = out + ((size_t)n * K_ + k) * C_;
#pragma unroll
    for (int i = 0; i < 4; i++) op[tid + i * 128] = v[i] * inv;
    if (tid == 0) atomicAdd(&g_gssq[n], rssq * inv * inv);
}

// ---------------- K4: global L2 scale ----------------
__global__ void k_scale(float* __restrict__ out) {
    int idx = blockIdx.x * 256 + threadIdx.x;     // grid 8192 x 256 = N*K*C exactly
    int n = idx >> 15;                            // / (K_*C_) = 32768
    float inv = 1.0f / fmaxf(sqrtf(g_gssq[n]), 1e-12f);
    out[idx] *= inv;
}

// ---------------- launch ----------------
extern "C" void kernel_launch(void* const* d_in, const int* in_sizes, int n_in,
                              void* d_out, int out_size) {
    const float* x    = (const float*)d_in[0];   // [N, C, H, W]
    const float* w    = (const float*)d_in[1];   // [K, C]
    const float* b    = (const float*)d_in[2];   // [K]
    const float* cent = (const float*)d_in[3];   // [K, C]
    float* out = (float*)d_out;                  // [N, K*C]

    k_init<<<128, 256>>>(w);
    k_logits<<<640, 160>>>(x, b);
    k_agg<<<dim3(4, 64), 256>>>(x);
    k_final<<<N_ * K_, 128>>>(cent, out);
    k_scale<<<8192, 256>>>(out);
}

// round 9
// speedup vs baseline: 2.4943x; 2.4943x over previous
#include <cuda_runtime.h>
#include <cuda_bf16.h>
#include <mma.h>
#include <math.h>
#include <stdint.h>

using namespace nvcuda;

#define N_  64
#define C_  512
#define M_  1600
#define K_  64
#define AP  72    // bf16 SMEM pitch (multiple of 8 for WMMA ldm)
#define LP  68    // fp32 epilogue pitch (multiple of 4)

// ---------------- device scratch ----------------
__device__ __nv_bfloat16 g_ah[(size_t)N_*K_*M_];   // assign hi (13.1 MB)
__device__ __nv_bfloat16 g_al[(size_t)N_*K_*M_];   // assign lo
__device__ float g_norms[N_*M_];
__device__ float g_agg[(size_t)N_*K_*C_];          // [n][k][c]
__device__ float g_gssq[N_];

static __device__ __forceinline__ uint32_t pack_bf(float lo, float hi) {
    __nv_bfloat162 t = __floats2bfloat162_rn(lo, hi);
    return *reinterpret_cast<uint32_t*>(&t);
}

// ---------------- K0 ----------------
__global__ void k_init() {
    if (threadIdx.x < N_) g_gssq[threadIdx.x] = 0.f;
}

// ---------------- GEMM1: logits + fused L2-norm + softmax -------------------
// grid (13, 64), 256 thr. dyn smem 55296 B:
//   Ah[128*AP] | Al[128*AP] | Wh[64*AP] | Wl[64*AP]  (bf16)
//   epilogue alias: logits fp32 [128][LP] (34816 B)
__global__ __launch_bounds__(256) void k_gemm1(const float* __restrict__ x,
                                               const float* __restrict__ conv_w,
                                               const float* __restrict__ conv_b) {
    extern __shared__ __align__(16) char dsm[];
    __nv_bfloat16* Ah = (__nv_bfloat16*)dsm;
    __nv_bfloat16* Al = Ah + 128 * AP;
    __nv_bfloat16* Wh = Al + 128 * AP;
    __nv_bfloat16* Wl = Wh + 64 * AP;
    float* logits = (float*)dsm;                 // alias (used after last sync)
    __shared__ float sb[64];
    __shared__ float sred[256];

    const int tid = threadIdx.x, wid = tid >> 5;
    const int n = blockIdx.y, m0 = blockIdx.x * 128;
    if (tid < 64) sb[tid] = conv_b[tid];

    const int mloc = tid & 127, cgrp = tid >> 7;
    const int m = m0 + mloc;
    const bool mv = m < M_;
    const float* xb = x + (size_t)n * C_ * M_ + m;

    wmma::fragment<wmma::accumulator, 16, 16, 16, float> acc[4];
#pragma unroll
    for (int kf = 0; kf < 4; kf++) wmma::fill_fragment(acc[kf], 0.f);

    float ssql = 0.f;

    for (int j = 0; j < 8; j++) {
        const int cb = j * 64;
        // ---- A tile [128m x 64c] hi/lo, ssq fused ----
#pragma unroll 4
        for (int i = 0; i < 16; i++) {
            int cl = 2 * cgrp + 4 * i;                  // even pair start
            float v0 = mv ? xb[(size_t)(cb + cl) * M_] : 0.f;
            float v1 = mv ? xb[(size_t)(cb + cl + 1) * M_] : 0.f;
            ssql = fmaf(v0, v0, fmaf(v1, v1, ssql));
            __nv_bfloat16 h0 = __float2bfloat16(v0), h1 = __float2bfloat16(v1);
            float r0 = v0 - __bfloat162float(h0), r1 = v1 - __bfloat162float(h1);
            *(uint32_t*)(Ah + mloc * AP + cl) = pack_bf(__bfloat162float(h0), __bfloat162float(h1));
            *(uint32_t*)(Al + mloc * AP + cl) = pack_bf(r0, r1);
        }
        // ---- W tile [64k x 64c] hi/lo ----
#pragma unroll 4
        for (int p = 0; p < 8; p++) {
            int k = (tid >> 5) + 8 * p;
            int cl = 2 * (tid & 31);
            float w0 = conv_w[k * C_ + cb + cl];
            float w1 = conv_w[k * C_ + cb + cl + 1];
            __nv_bfloat16 h0 = __float2bfloat16(w0), h1 = __float2bfloat16(w1);
            float r0 = w0 - __bfloat162float(h0), r1 = w1 - __bfloat162float(h1);
            *(uint32_t*)(Wh + k * AP + cl) = pack_bf(__bfloat162float(h0), __bfloat162float(h1));
            *(uint32_t*)(Wl + k * AP + cl) = pack_bf(r0, r1);
        }
        __syncthreads();
        // ---- MMA: warp owns m-rows [16*wid, 16*wid+16) ----
        wmma::fragment<wmma::matrix_a, 16, 16, 16, __nv_bfloat16, wmma::row_major> fah, fal;
        wmma::fragment<wmma::matrix_b, 16, 16, 16, __nv_bfloat16, wmma::col_major> fbh, fbl;
#pragma unroll
        for (int cs = 0; cs < 4; cs++) {
            wmma::load_matrix_sync(fah, Ah + wid * 16 * AP + cs * 16, AP);
            wmma::load_matrix_sync(fal, Al + wid * 16 * AP + cs * 16, AP);
#pragma unroll
            for (int kf = 0; kf < 4; kf++) {
                wmma::load_matrix_sync(fbh, Wh + kf * 16 * AP + cs * 16, AP);
                wmma::load_matrix_sync(fbl, Wl + kf * 16 * AP + cs * 16, AP);
                wmma::mma_sync(acc[kf], fah, fbh, acc[kf]);
                wmma::mma_sync(acc[kf], fah, fbl, acc[kf]);
                wmma::mma_sync(acc[kf], fal, fbh, acc[kf]);
            }
        }
        __syncthreads();
    }

    sred[tid] = ssql;
    __syncthreads();
#pragma unroll
    for (int kf = 0; kf < 4; kf++)
        wmma::store_matrix_sync(logits + wid * 16 * LP + kf * 16, acc[kf], LP,
                                wmma::mem_row_major);
    __syncthreads();

    // ---- softmax epilogue: one thread per m row ----
    if (tid < 128) {
        const int mm = m0 + tid;
        if (mm < M_) {
            float ssq = sred[tid] + sred[tid + 128];
            const float nrm = fmaxf(sqrtf(ssq), 1e-12f);
            const float inv = 1.0f / nrm;
            float lg[64];
            float mx = -1e30f;
#pragma unroll
            for (int k = 0; k < 64; k++) {
                float f = fmaf(logits[tid * LP + k], inv, sb[k]);
                lg[k] = f;
                mx = fmaxf(mx, f);
            }
            float s = 0.f;
#pragma unroll
            for (int k = 0; k < 64; k++) { float e = __expf(lg[k] - mx); lg[k] = e; s += e; }
            const float rs = inv / s;
            g_norms[n * M_ + mm] = nrm;
            __nv_bfloat16* ah = g_ah + (size_t)n * K_ * M_ + mm;
            __nv_bfloat16* al = g_al + (size_t)n * K_ * M_ + mm;
#pragma unroll
            for (int k = 0; k < 64; k++) {
                float p = lg[k] * rs;
                __nv_bfloat16 h = __float2bfloat16(p);
                ah[(size_t)k * M_] = h;
                al[(size_t)k * M_] = __float2bfloat16(p - __bfloat162float(h));
            }
        }
    }
}

// ---------------- GEMM2: agg[c,k] = sum_m x[c,m] * A'[k,m] -------------------
// grid (4, 64), 256 thr. dyn smem 55296 B:
//   Xh[128*AP] | Xl[128*AP] | Bh[64*AP] | Bl[64*AP]
//   epilogue alias: tr fp32 [128][LP]
__global__ __launch_bounds__(256) void k_gemm2(const float* __restrict__ x) {
    extern __shared__ __align__(16) char dsm[];
    __nv_bfloat16* Xh = (__nv_bfloat16*)dsm;
    __nv_bfloat16* Xl = Xh + 128 * AP;
    __nv_bfloat16* Bh = Xl + 128 * AP;
    __nv_bfloat16* Bl = Bh + 64 * AP;
    float* tr = (float*)dsm;

    const int tid = threadIdx.x, wid = tid >> 5;
    const int n = blockIdx.y, c0 = blockIdx.x * 128;
    const int mh = tid & 31;            // m-pair lane
    const int mloc = 2 * mh;

    wmma::fragment<wmma::accumulator, 16, 16, 16, float> acc[4];
#pragma unroll
    for (int kf = 0; kf < 4; kf++) wmma::fill_fragment(acc[kf], 0.f);

    for (int j = 0; j < 25; j++) {                 // 1600 = 25 * 64 exact
        const int m0 = j * 64;
        const float* xb = x + ((size_t)n * C_ + c0) * M_ + m0 + mloc;
        // ---- X tile [128c x 64m] hi/lo ----
#pragma unroll 4
        for (int i = 0; i < 16; i++) {
            int c = (tid >> 5) + 8 * i;
            float2 v = *(const float2*)(xb + (size_t)c * M_);
            __nv_bfloat16 h0 = __float2bfloat16(v.x), h1 = __float2bfloat16(v.y);
            float r0 = v.x - __bfloat162float(h0), r1 = v.y - __bfloat162float(h1);
            *(uint32_t*)(Xh + c * AP + mloc) = pack_bf(__bfloat162float(h0), __bfloat162float(h1));
            *(uint32_t*)(Xl + c * AP + mloc) = pack_bf(r0, r1);
        }
        // ---- B tile [64k x 64m] from pre-split bf16 assign ----
        const __nv_bfloat16* ah = g_ah + (size_t)n * K_ * M_ + m0 + mloc;
        const __nv_bfloat16* al = g_al + (size_t)n * K_ * M_ + m0 + mloc;
#pragma unroll 4
        for (int i = 0; i < 8; i++) {
            int k = (tid >> 5) + 8 * i;
            *(uint32_t*)(Bh + k * AP + mloc) = *(const uint32_t*)(ah + (size_t)k * M_);
            *(uint32_t*)(Bl + k * AP + mloc) = *(const uint32_t*)(al + (size_t)k * M_);
        }
        __syncthreads();
        // ---- MMA: warp owns c-rows [16*wid, +16) ----
        wmma::fragment<wmma::matrix_a, 16, 16, 16, __nv_bfloat16, wmma::row_major> fah, fal;
        wmma::fragment<wmma::matrix_b, 16, 16, 16, __nv_bfloat16, wmma::col_major> fbh, fbl;
#pragma unroll
        for (int ms = 0; ms < 4; ms++) {
            wmma::load_matrix_sync(fah, Xh + wid * 16 * AP + ms * 16, AP);
            wmma::load_matrix_sync(fal, Xl + wid * 16 * AP + ms * 16, AP);
#pragma unroll
            for (int kf = 0; kf < 4; kf++) {
                wmma::load_matrix_sync(fbh, Bh + kf * 16 * AP + ms * 16, AP);
                wmma::load_matrix_sync(fbl, Bl + kf * 16 * AP + ms * 16, AP);
                wmma::mma_sync(acc[kf], fah, fbh, acc[kf]);
                wmma::mma_sync(acc[kf], fah, fbl, acc[kf]);
                wmma::mma_sync(acc[kf], fal, fbh, acc[kf]);
            }
        }
        __syncthreads();
    }

    // ---- epilogue: D[128c x 64k] -> SMEM -> coalesced [k][c] stores ----
#pragma unroll
    for (int kf = 0; kf < 4; kf++)
        wmma::store_matrix_sync(tr + wid * 16 * LP + kf * 16, acc[kf], LP,
                                wmma::mem_row_major);
    __syncthreads();
#pragma unroll 4
    for (int p = 0; p < 32; p++) {
        int idx = tid + 256 * p;                    // 8192 = 64k * 128c
        int k = idx >> 7, cc = idx & 127;
        g_agg[((size_t)n * K_ + k) * C_ + c0 + cc] = tr[cc * LP + k];
    }
}

// ---------------- K3: finalize per (n,k): a_sum, residual, intra-norm --------
__global__ __launch_bounds__(128) void k_final(const float* __restrict__ cent,
                                               float* __restrict__ out) {
    const int n = blockIdx.x >> 6, k = blockIdx.x & 63;
    const int tid = threadIdx.x;
    __shared__ float red[128];

    const __nv_bfloat16* ah = g_ah + ((size_t)n * K_ + k) * M_;
    const __nv_bfloat16* al = g_al + ((size_t)n * K_ + k) * M_;
    const float* np = g_norms + n * M_;
    float s = 0.f;
    for (int m = tid; m < M_; m += 128) {
        float a = __bfloat162float(ah[m]) + __bfloat162float(al[m]);
        s = fmaf(a, np[m], s);
    }
    red[tid] = s;
    __syncthreads();
    for (int off = 64; off > 0; off >>= 1) {
        if (tid < off) red[tid] += red[tid + off];
        __syncthreads();
    }
    const float asum = red[0];
    __syncthreads();

    const float* gp = g_agg + ((size_t)n * K_ + k) * C_;
    const float* cp = cent + k * C_;
    float v[4], ssq = 0.f;
#pragma unroll
    for (int i = 0; i < 4; i++) {
        int c = tid + i * 128;
        v[i] = gp[c] - asum * cp[c];
        ssq = fmaf(v[i], v[i], ssq);
    }
    red[tid] = ssq;
    __syncthreads();
    for (int off = 64; off > 0; off >>= 1) {
        if (tid < off) red[tid] += red[tid + off];
        __syncthreads();
    }
    const float rssq = red[0];
    const float inv = 1.0f / fmaxf(sqrtf(rssq), 1e-12f);
    float* op = out + ((size_t)n * K_ + k) * C_;
#pragma unroll
    for (int i = 0; i < 4; i++) op[tid + i * 128] = v[i] * inv;
    if (tid == 0) atomicAdd(&g_gssq[n], rssq * inv * inv);
}

// ---------------- K4: global L2 scale ----------------
__global__ void k_scale(float* __restrict__ out) {
    int idx = blockIdx.x * 256 + threadIdx.x;     // 8192*256 = N*K*C exactly
    int n = idx >> 15;                            // / 32768
    float inv = 1.0f / fmaxf(sqrtf(g_gssq[n]), 1e-12f);
    out[idx] *= inv;
}

// ---------------- launch ----------------
extern "C" void kernel_launch(void* const* d_in, const int* in_sizes, int n_in,
                              void* d_out, int out_size) {
    const float* x    = (const float*)d_in[0];
    const float* w    = (const float*)d_in[1];
    const float* b    = (const float*)d_in[2];
    const float* cent = (const float*)d_in[3];
    float* out = (float*)d_out;

    const int smem = (128 + 64) * AP * 2 * 2;     // 55296 B
    cudaFuncSetAttribute(k_gemm1, cudaFuncAttributeMaxDynamicSharedMemorySize, smem);
    cudaFuncSetAttribute(k_gemm2, cudaFuncAttributeMaxDynamicSharedMemorySize, smem);

    k_init<<<1, 64>>>();
    k_gemm1<<<dim3(13, 64), 256, smem>>>(x, w, b);
    k_gemm2<<<dim3(4, 64), 256, smem>>>(x);
    k_final<<<N_ * K_, 128>>>(cent, out);
    k_scale<<<8192, 256>>>(out);
}

// round 11
// speedup vs baseline: 3.8477x; 1.5426x over previous
#include <cuda_runtime.h>
#include <cuda_fp16.h>
#include <mma.h>
#include <math.h>
#include <stdint.h>

using namespace nvcuda;

#define N_  64
#define C_  512
#define M_  1600
#define K_  64
#define AP  72    // half SMEM pitch (mult of 8; 144B rows, 16B aligned)
#define LP  68    // fp32 epilogue pitch

// ---------------- device scratch ----------------
__device__ __half g_ah[(size_t)N_*K_*M_];      // assign' = softmax*invnorm (fp16, 13.1 MB)
__device__ float g_agg[(size_t)N_*K_*C_];      // [n][k][c]
__device__ float g_asum[N_*K_];                // sum_m softmax
__device__ float g_gssq[N_];

// ---------------- K0: zero accumulators ----------------
__global__ void k_init() {
    int idx = blockIdx.x * 256 + threadIdx.x;
    if (idx < N_ * K_) g_asum[idx] = 0.f;
    if (idx < N_) g_gssq[idx] = 0.f;
}

// ---------------- GEMM1: logits + fused L2-norm + softmax + a_sum ----------
// grid (13, 64), 256 thr. dyn smem 34816 B:
//   mainloop: Ah[128*AP] | Wh[64*AP] (half)
//   epilogue alias: pbuf fp32 [128][LP]
__global__ __launch_bounds__(256) void k_gemm1(const float* __restrict__ x,
                                               const float* __restrict__ conv_w,
                                               const float* __restrict__ conv_b) {
    extern __shared__ __align__(16) char dsm[];
    __half* Ah = (__half*)dsm;
    __half* Wh = Ah + 128 * AP;
    float* pbuf = (float*)dsm;                  // alias, used after mainloop
    __shared__ float sb[64];
    __shared__ float sred[256], sA[256], sS[256];

    const int tid = threadIdx.x, wid = tid >> 5;
    const int n = blockIdx.y, m0 = blockIdx.x * 128;
    if (tid < 64) sb[tid] = conv_b[tid];

    const int mloc = tid & 127, cgrp = tid >> 7;
    const int m = m0 + mloc;
    const bool mv = m < M_;
    const float* xb = x + (size_t)n * C_ * M_ + m;

    wmma::fragment<wmma::accumulator, 16, 16, 16, float> acc[4];
#pragma unroll
    for (int kf = 0; kf < 4; kf++) wmma::fill_fragment(acc[kf], 0.f);

    float ssql = 0.f;

    for (int j = 0; j < 8; j++) {
        const int cb = j * 64;
        // A tile [128m x 64c] fp16, ssq fused
#pragma unroll 4
        for (int i = 0; i < 16; i++) {
            int cl = 2 * cgrp + 4 * i;
            float v0 = mv ? xb[(size_t)(cb + cl) * M_] : 0.f;
            float v1 = mv ? xb[(size_t)(cb + cl + 1) * M_] : 0.f;
            ssql = fmaf(v0, v0, fmaf(v1, v1, ssql));
            *(__half2*)(Ah + mloc * AP + cl) = __floats2half2_rn(v0, v1);
        }
        // W tile [64k x 64c] fp16
#pragma unroll 4
        for (int p = 0; p < 8; p++) {
            int k = (tid >> 5) + 8 * p;
            int cl = 2 * (tid & 31);
            *(__half2*)(Wh + k * AP + cl) =
                __floats2half2_rn(conv_w[k * C_ + cb + cl], conv_w[k * C_ + cb + cl + 1]);
        }
        __syncthreads();
        wmma::fragment<wmma::matrix_a, 16, 16, 16, __half, wmma::row_major> fa;
        wmma::fragment<wmma::matrix_b, 16, 16, 16, __half, wmma::col_major> fb;
#pragma unroll
        for (int cs = 0; cs < 4; cs++) {
            wmma::load_matrix_sync(fa, Ah + wid * 16 * AP + cs * 16, AP);
#pragma unroll
            for (int kf = 0; kf < 4; kf++) {
                wmma::load_matrix_sync(fb, Wh + kf * 16 * AP + cs * 16, AP);
                wmma::mma_sync(acc[kf], fa, fb, acc[kf]);
            }
        }
        __syncthreads();
    }

    sred[tid] = ssql;
    __syncthreads();
#pragma unroll
    for (int kf = 0; kf < 4; kf++)
        wmma::store_matrix_sync(pbuf + wid * 16 * LP + kf * 16, acc[kf], LP,
                                wmma::mem_row_major);
    __syncthreads();

    // softmax: 2 threads per m row (tid<128: k 0..31; tid>=128: k 32..63)
    const int mm = tid & 127;
    const int kh = (tid >> 7) * 32;
    const bool valid = (m0 + mm) < M_;
    const float ssq = sred[mm] + sred[mm + 128];
    const float nrm = fmaxf(sqrtf(ssq), 1e-12f);
    const float inv = 1.0f / nrm;
    float lg[32];
    float mx = -1e30f;
#pragma unroll
    for (int jj = 0; jj < 32; jj++) {
        float f = fmaf(pbuf[mm * LP + kh + jj], inv, sb[kh + jj]);
        lg[jj] = f;
        mx = fmaxf(mx, f);
    }
    sA[tid] = mx;
    __syncthreads();
    mx = fmaxf(sA[mm], sA[mm + 128]);
    float s = 0.f;
#pragma unroll
    for (int jj = 0; jj < 32; jj++) {
        float e = __expf(lg[jj] - mx);
        lg[jj] = e;
        s += e;
    }
    sS[tid] = s;
    __syncthreads();
    s = sS[mm] + sS[mm + 128];
    const float rs = 1.0f / s;
#pragma unroll
    for (int jj = 0; jj < 32; jj++)
        pbuf[mm * LP + kh + jj] = valid ? lg[jj] * rs : 0.f;   // softmax for a_sum
    if (valid) {
        __half* ah = g_ah + ((size_t)n * K_ + kh) * M_ + m0 + mm;
        const float ri = rs * inv;
#pragma unroll
        for (int jj = 0; jj < 32; jj++)
            ah[(size_t)jj * M_] = __float2half(lg[jj] * ri);   // softmax*invnorm
    }
    __syncthreads();
    // a_sum partial: thread k sums softmax over the block's 128 m rows
    if (tid < 64) {
        float s2 = 0.f;
        for (int r = 0; r < 128; r++) s2 += pbuf[r * LP + tid];
        atomicAdd(&g_asum[n * K_ + tid], s2);
    }
}

// ---------------- GEMM2: agg[c,k] = sum_m x[c,m] * A'[k,m] -------------------
// grid (4, 64), 256 thr. dyn smem 34816 B: Xh[128*AP] | Bh[64*AP]; alias tr[128][LP]
__global__ __launch_bounds__(256) void k_gemm2(const float* __restrict__ x) {
    extern __shared__ __align__(16) char dsm[];
    __half* Xh = (__half*)dsm;
    __half* Bh = Xh + 128 * AP;
    float* tr = (float*)dsm;

    const int tid = threadIdx.x, wid = tid >> 5;
    const int n = blockIdx.y, c0 = blockIdx.x * 128;
    const int mloc = 2 * (tid & 31);

    wmma::fragment<wmma::accumulator, 16, 16, 16, float> acc[4];
#pragma unroll
    for (int kf = 0; kf < 4; kf++) wmma::fill_fragment(acc[kf], 0.f);

    for (int j = 0; j < 25; j++) {                 // 1600 = 25 * 64 exact
        const int m0 = j * 64;
        const float* xb = x + ((size_t)n * C_ + c0) * M_ + m0 + mloc;
        // X tile [128c x 64m] fp16
#pragma unroll 4
        for (int i = 0; i < 16; i++) {
            int c = (tid >> 5) + 8 * i;
            float2 v = *(const float2*)(xb + (size_t)c * M_);
            *(__half2*)(Xh + c * AP + mloc) = __floats2half2_rn(v.x, v.y);
        }
        // B tile [64k x 64m] copied from fp16 assign
        const __half* ah = g_ah + (size_t)n * K_ * M_ + m0 + mloc;
#pragma unroll 4
        for (int i = 0; i < 8; i++) {
            int k = (tid >> 5) + 8 * i;
            *(uint32_t*)(Bh + k * AP + mloc) = *(const uint32_t*)(ah + (size_t)k * M_);
        }
        __syncthreads();
        wmma::fragment<wmma::matrix_a, 16, 16, 16, __half, wmma::row_major> fa;
        wmma::fragment<wmma::matrix_b, 16, 16, 16, __half, wmma::col_major> fb;
#pragma unroll
        for (int ms = 0; ms < 4; ms++) {
            wmma::load_matrix_sync(fa, Xh + wid * 16 * AP + ms * 16, AP);
#pragma unroll
            for (int kf = 0; kf < 4; kf++) {
                wmma::load_matrix_sync(fb, Bh + kf * 16 * AP + ms * 16, AP);
                wmma::mma_sync(acc[kf], fa, fb, acc[kf]);
            }
        }
        __syncthreads();
    }

    // epilogue: D[128c x 64k] -> SMEM -> coalesced [k][c] stores
#pragma unroll
    for (int kf = 0; kf < 4; kf++)
        wmma::store_matrix_sync(tr + wid * 16 * LP + kf * 16, acc[kf], LP,
                                wmma::mem_row_major);
    __syncthreads();
#pragma unroll 4
    for (int p = 0; p < 32; p++) {
        int idx = tid + 256 * p;                    // 8192 = 64k * 128c
        int k = idx >> 7, cc = idx & 127;
        g_agg[((size_t)n * K_ + k) * C_ + c0 + cc] = tr[cc * LP + k];
    }
}

// ---------------- K3: finalize per (n,k): residual + intra-norm --------------
__global__ __launch_bounds__(128) void k_final(const float* __restrict__ cent,
                                               float* __restrict__ out) {
    const int n = blockIdx.x >> 6, k = blockIdx.x & 63;
    const int tid = threadIdx.x;
    __shared__ float red[128];

    const float asum = g_asum[n * K_ + k];
    const float* gp = g_agg + ((size_t)n * K_ + k) * C_;
    const float* cp = cent + k * C_;
    float v[4], ssq = 0.f;
#pragma unroll
    for (int i = 0; i < 4; i++) {
        int c = tid + i * 128;
        v[i] = gp[c] - asum * cp[c];
        ssq = fmaf(v[i], v[i], ssq);
    }
    red[tid] = ssq;
    __syncthreads();
    for (int off = 64; off > 0; off >>= 1) {
        if (tid < off) red[tid] += red[tid + off];
        __syncthreads();
    }
    const float rssq = red[0];
    const float inv = 1.0f / fmaxf(sqrtf(rssq), 1e-12f);
    float* op = out + ((size_t)n * K_ + k) * C_;
#pragma unroll
    for (int i = 0; i < 4; i++) op[tid + i * 128] = v[i] * inv;
    if (tid == 0) atomicAdd(&g_gssq[n], rssq * inv * inv);
}

// ---------------- K4: global L2 scale ----------------
__global__ void k_scale(float* __restrict__ out) {
    int idx = blockIdx.x * 256 + threadIdx.x;     // 8192*256 = N*K*C exactly
    int n = idx >> 15;
    float inv = 1.0f / fmaxf(sqrtf(g_gssq[n]), 1e-12f);
    out[idx] *= inv;
}

// ---------------- launch ----------------
extern "C" void kernel_launch(void* const* d_in, const int* in_sizes, int n_in,
                              void* d_out, int out_size) {
    const float* x    = (const float*)d_in[0];
    const float* w    = (const float*)d_in[1];
    const float* b    = (const float*)d_in[2];
    const float* cent = (const float*)d_in[3];
    float* out = (float*)d_out;

    const int smem = 128 * LP * 4;                // 34816 B (<48KB default cap)

    k_init<<<17, 256>>>();
    k_gemm1<<<dim3(13, 64), 256, smem>>>(x, w, b);
    k_gemm2<<<dim3(4, 64), 256, smem>>>(x);
    k_final<<<N_ * K_, 128>>>(cent, out);
    k_scale<<<8192, 256>>>(out);
}